// round 16
// baseline (speedup 1.0000x reference)
#include <cuda_runtime.h>
#include <cuda_fp16.h>

// ---------------------------------------------------------------------------
// LSTM forecaster via fp16 tensor-core MMA (mma.sync.m16n8k16, fp32 accum).
//
// Per CTA: 64 batch rows, whole 50-step recurrence local.
// A (smem, fp16): hcat rows = [h0(128) | x/y(16) | h1(128) | pad], stride 296.
// B (smem, fp16): per-warp PRIVATE weight slabs, 32 k-columns per chunk
//   (two 16-k MMA steps per staged chunk), cp.async DOUBLE-buffered ring,
//   cp.async.wait_group 1, no per-chunk __syncthreads.
//   Weight images (fp16, built by prep kernel in device global memory):
//     encL0: [eWhh0 | eWih0 | 0pad]   K=160  (5 chunks; k>=138 zero)
//     encL1: [eWih1 | eWhh1]          K=256  (8 chunks; A skips x/y slot)
//     decL0: [dWhh0 | dWih0 | 0pad]   K=160
//     decL1: [dWih1 | dWhh1]          K=256
// Warp w owns gate columns {g*128 + 8w .. +8} for g=0..3 -> each thread holds
// i,f,g,o of its cells in registers after MMA; elementwise finish is
// register-local; c-state fp32 in smem; h written back fp16 into hcat.
// ---------------------------------------------------------------------------

#define THREADS 512
#define HID     128
#define GATES   512
#define ROWS    64
#define HS      296      // hcat stride (halves)
#define CS      132      // c-state stride (floats)
#define T_HIST  20
#define T_FUT   30
#define FIN     10

// per-warp weight slab: 32 rows (4 gates x 8 j) x 80B (32 halves + 8 pad)
#define WSTRB   80
#define GSTRB   640            // 8 rows * 80B per gate block
#define SLABB   2560           // 32 * 80
#define NRING   2

// weight image geometry (halves)
#define K_L0    160
#define K_L1    256
#define NK_L0   5              // 160/32
#define NK_L1   8              // 256/32
#define SZ_L0   (512*K_L0)     // 81920
#define SZ_L1   (512*K_L1)     // 131072
#define OFF_E0  0
#define OFF_E1  (SZ_L0)
#define OFF_D0  (SZ_L0 + SZ_L1)
#define OFF_D1  (2*SZ_L0 + SZ_L1)
#define WIMG_TOTAL (2*SZ_L0 + 2*SZ_L1)   // 425984

// smem layout (bytes)
#define WBUF_OFF  0
#define WBUF_SZ   (16*NRING*SLABB)              // 81920
#define HCAT_OFF  (WBUF_OFF + WBUF_SZ)          // 81920
#define CST0_OFF  (HCAT_OFF + ROWS*HS*2)        // +37888 = 119808
#define CST1_OFF  (CST0_OFF + ROWS*CS*4)        // +33792 = 153600
#define BIAS_OFF  (CST1_OFF + ROWS*CS*4)        // +33792 = 187392
#define HEADW_OFF (BIAS_OFF + 4*GATES*4)        // +8192  = 195584
#define HEADB_OFF (HEADW_OFF + 1024)            // 196608
#define SMEM_BYTES (HEADB_OFF + 32)             // 196640

__device__ __align__(16) __half g_wimg[WIMG_TOTAL];

// ---------------- device helpers ----------------
__device__ __forceinline__ float sigf(float x) {
    return __fdividef(1.0f, 1.0f + __expf(-x));
}
__device__ __forceinline__ float tanhf_fast(float x) {
    return 1.0f - __fdividef(2.0f, __expf(2.0f * x) + 1.0f);
}
__device__ __forceinline__ unsigned int smem_u32(const void* p) {
    unsigned int a;
    asm("{ .reg .u64 t; cvta.to.shared.u64 t, %1; cvt.u32.u64 %0, t; }"
        : "=r"(a) : "l"(p));
    return a;
}
__device__ __forceinline__ void cp_async16(unsigned int dst, const void* src) {
    asm volatile("cp.async.cg.shared.global [%0], [%1], 16;"
                 :: "r"(dst), "l"(src) : "memory");
}
__device__ __forceinline__ void cp_commit() {
    asm volatile("cp.async.commit_group;" ::: "memory");
}
__device__ __forceinline__ void cp_wait1() {
    asm volatile("cp.async.wait_group 1;" ::: "memory");
}
__device__ __forceinline__ void cp_wait0() {
    asm volatile("cp.async.wait_group 0;" ::: "memory");
}
__device__ __forceinline__ void ldsm_x4(unsigned int* r, unsigned int addr) {
    asm volatile("ldmatrix.sync.aligned.m8n8.x4.shared.b16 {%0,%1,%2,%3}, [%4];"
                 : "=r"(r[0]), "=r"(r[1]), "=r"(r[2]), "=r"(r[3]) : "r"(addr));
}
__device__ __forceinline__ void ldsm_x2(unsigned int& r0, unsigned int& r1,
                                        unsigned int addr) {
    asm volatile("ldmatrix.sync.aligned.m8n8.x2.shared.b16 {%0,%1}, [%2];"
                 : "=r"(r0), "=r"(r1) : "r"(addr));
}
__device__ __forceinline__ void mma16816(float* d, const unsigned int* a,
                                         unsigned int b0, unsigned int b1) {
    asm volatile(
        "mma.sync.aligned.m16n8k16.row.col.f32.f16.f16.f32 "
        "{%0,%1,%2,%3},{%4,%5,%6,%7},{%8,%9},{%0,%1,%2,%3};"
        : "+f"(d[0]), "+f"(d[1]), "+f"(d[2]), "+f"(d[3])
        : "r"(a[0]), "r"(a[1]), "r"(a[2]), "r"(a[3]), "r"(b0), "r"(b1));
}

// ---------------- prep kernel: fp32 weights -> fp16 concat images ----------
__global__ void prep_weights(const float* __restrict__ eWih0, const float* __restrict__ eWhh0,
                             const float* __restrict__ eWih1, const float* __restrict__ eWhh1,
                             const float* __restrict__ dWih0, const float* __restrict__ dWhh0,
                             const float* __restrict__ dWih1, const float* __restrict__ dWhh1)
{
    int idx = blockIdx.x * blockDim.x + threadIdx.x;
    if (idx >= WIMG_TOTAL) return;
    float v = 0.0f;
    if (idx < OFF_E1) {                       // encL0 [eWhh0 | eWih0 | 0]
        int i = idx, g = i / K_L0, k = i - g * K_L0;
        if (k < 128)       v = eWhh0[g * 128 + k];
        else if (k < 138)  v = eWih0[g * FIN + (k - 128)];
    } else if (idx < OFF_D0) {                // encL1 [eWih1 | eWhh1]
        int i = idx - OFF_E1, g = i / K_L1, k = i - g * K_L1;
        if (k < 128)       v = eWih1[g * 128 + k];
        else               v = eWhh1[g * 128 + (k - 128)];
    } else if (idx < OFF_D1) {                // decL0 [dWhh0 | dWih0 | 0]
        int i = idx - OFF_D0, g = i / K_L0, k = i - g * K_L0;
        if (k < 128)       v = dWhh0[g * 128 + k];
        else if (k < 130)  v = dWih0[g * 2 + (k - 128)];
    } else {                                  // decL1 [dWih1 | dWhh1]
        int i = idx - OFF_D1, g = i / K_L1, k = i - g * K_L1;
        if (k < 128)       v = dWih1[g * 128 + k];
        else               v = dWhh1[g * 128 + (k - 128)];
    }
    g_wimg[idx] = __float2half(v);
}

// ---------------- main kernel ----------------
__global__ void __launch_bounds__(THREADS, 1)
lstm_mma_kernel(const float* __restrict__ hist,
                const float* __restrict__ ebih0, const float* __restrict__ ebhh0,
                const float* __restrict__ ebih1, const float* __restrict__ ebhh1,
                const float* __restrict__ dbih0, const float* __restrict__ dbhh0,
                const float* __restrict__ dbih1, const float* __restrict__ dbhh1,
                const float* __restrict__ headW, const float* __restrict__ headb,
                float* __restrict__ out)
{
    extern __shared__ char smraw[];
    __half* hcat  = (__half*)(smraw + HCAT_OFF);
    float*  cst0  = (float*)(smraw + CST0_OFF);
    float*  cst1  = (float*)(smraw + CST1_OFF);
    float*  bias  = (float*)(smraw + BIAS_OFF);   // 4 x 512
    float*  headWs= (float*)(smraw + HEADW_OFF);  // 256
    float*  headbs= (float*)(smraw + HEADB_OFF);  // 2

    const int tid  = threadIdx.x;
    const int lane = tid & 31;
    const int warp = tid >> 5;
    const int tg   = lane >> 2;       // 0..7
    const int tp   = lane & 3;        // 0..3
    const int j0   = warp * 8;        // hidden-j base for this warp
    const int brow = blockIdx.x * ROWS;

    const unsigned int wbase = smem_u32(smraw + WBUF_OFF)
                             + (unsigned)(warp * NRING * SLABB);
    const unsigned int hcat_u32 = smem_u32(hcat);

    // ldmatrix A addressing
    const int arow = (lane & 7) + (((lane >> 3) & 1) << 3);
    const unsigned int aoff = (unsigned)((arow * HS + ((lane >> 4) & 1) * 8) * 2);
    // ldmatrix B sub-offset within warp slab
    const int l2 = lane & 15;
    const unsigned int bsub = (unsigned)((l2 & 7) * WSTRB + ((l2 >> 3) & 1) * 16);
    // staging coords: lane -> slab row (gate lane>>3, j-row lane&7)
    const int sg = lane >> 3;
    const int sr = lane & 7;

    // stage chunk c (32 k-cols) of image into ring slot `slot` (warp-private)
    auto stage = [&](const __half* img, int Kimg, int c, int slot) {
        unsigned int dst = wbase + (unsigned)(slot * SLABB + lane * WSTRB);
        const __half* src = img + (sg * 128 + j0 + sr) * Kimg + c * 32;
        cp_async16(dst,      src);
        cp_async16(dst + 16, src + 8);
        cp_async16(dst + 32, src + 16);
        cp_async16(dst + 48, src + 24);
        cp_commit();
    };

    // ---- prologue: zero state, load biases/head ----
    for (int i = tid; i < ROWS * HS; i += THREADS) hcat[i] = __float2half(0.0f);
    for (int i = tid; i < ROWS * CS; i += THREADS) { cst0[i] = 0.0f; cst1[i] = 0.0f; }
    {
        int i = tid;  // THREADS == GATES
        bias[i]        = ebih0[i] + ebhh0[i];
        bias[512 + i]  = ebih1[i] + ebhh1[i];
        bias[1024 + i] = dbih0[i] + dbhh0[i];
        bias[1536 + i] = dbih1[i] + dbhh1[i];
    }
    if (tid < 256) headWs[tid] = headW[tid];
    if (tid < 2)   headbs[tid] = headb[tid];

    const __half* IMG_E0 = g_wimg + OFF_E0;
    const __half* IMG_E1 = g_wimg + OFF_E1;
    const __half* IMG_D0 = g_wimg + OFF_D0;
    const __half* IMG_D1 = g_wimg + OFF_D1;

    // pipeline prologue: chunk 0 of first matrix into slot 0
    stage(IMG_E0, K_L0, 0, 0);
    int rslot = 0;
    __syncthreads();

    float acc[4][4][4];   // [mtile][gate][creg]

    auto init_acc = [&](const float* bs) {
        const int jc = j0 + 2 * tp;
#pragma unroll
        for (int g = 0; g < 4; ++g) {
            float b0 = bs[g * 128 + jc];
            float b1 = bs[g * 128 + jc + 1];
#pragma unroll
            for (int m = 0; m < 4; ++m) {
                acc[m][g][0] = b0; acc[m][g][1] = b1;
                acc[m][g][2] = b0; acc[m][g][3] = b1;
            }
        }
    };

    // one matrix: nchunks staged chunks, 2 MMA k-steps per chunk.
    // xgap=1: A column index skips the 16-col x/y slot after 8 k-steps (L1).
    auto run_matrix = [&](const __half* img, int Kimg, int nchunks,
                          const __half* nimg, int nKimg, int xgap) {
#pragma unroll 1
        for (int c = 0; c < nchunks; ++c) {
            int nslot = rslot ^ 1;
            if (c + 1 < nchunks) stage(img,  Kimg,  c + 1, nslot);
            else                 stage(nimg, nKimg, 0,     nslot);

            // A loads for both k-steps (independent of staging) before wait
            unsigned int a[2][4][4];
#pragma unroll
            for (int ks = 0; ks < 2; ++ks) {
                int kg  = 2 * c + ks;
                int col = kg + ((xgap && kg >= 8) ? 1 : 0);
#pragma unroll
                for (int m = 0; m < 4; ++m)
                    ldsm_x4(a[ks][m],
                            hcat_u32 + aoff + (unsigned)((m * 16 * HS + col * 16) * 2));
            }

            cp_wait1();   // chunk c slab landed (committed one chunk ago)

            const unsigned int bb = wbase + (unsigned)(rslot * SLABB) + bsub;
#pragma unroll
            for (int ks = 0; ks < 2; ++ks) {
                unsigned int b0[4], b1[4];
#pragma unroll
                for (int g = 0; g < 4; ++g)
                    ldsm_x2(b0[g], b1[g], bb + (unsigned)(g * GSTRB + ks * 32));
#pragma unroll
                for (int g = 0; g < 4; ++g)
#pragma unroll
                    for (int m = 0; m < 4; ++m)
                        mma16816(acc[m][g], a[ks][m], b0[g], b1[g]);
            }
            rslot ^= 1;
        }
        __syncthreads();   // all warps' hcat reads complete before overwrite
    };

    auto finish = [&](float* cs, int outcol) {
#pragma unroll
        for (int m = 0; m < 4; ++m) {
#pragma unroll
            for (int rr = 0; rr < 2; ++rr) {
                const int row = m * 16 + tg + rr * 8;
                const int jc  = j0 + 2 * tp;
                float hv[2];
#pragma unroll
                for (int cc = 0; cc < 2; ++cc) {
                    const int ci = rr * 2 + cc;
                    float gi = sigf(acc[m][0][ci]);
                    float gf = sigf(acc[m][1][ci]);
                    float gg = tanhf_fast(acc[m][2][ci]);
                    float go = sigf(acc[m][3][ci]);
                    float cold = cs[row * CS + jc + cc];
                    float cn = gf * cold + gi * gg;
                    cs[row * CS + jc + cc] = cn;
                    hv[cc] = go * tanhf_fast(cn);
                }
                *(__half2*)(hcat + row * HS + outcol + jc) =
                    __floats2half2_rn(hv[0], hv[1]);
            }
        }
        __syncthreads();   // new h visible to all warps before next matrix
    };

    // ================= encoder =================
#pragma unroll 1
    for (int t = 0; t < T_HIST; ++t) {
        // write x(t) into hcat cols 128..137; cols 138..143 stay 0
        for (int i = tid; i < ROWS * FIN; i += THREADS) {
            int r = i / FIN, f = i - r * FIN;
            hcat[r * HS + 128 + f] =
                __float2half(hist[(size_t)(brow + r) * (T_HIST * FIN) + t * FIN + f]);
        }
        __syncthreads();   // x visible before encL0 reads

        init_acc(bias);
        run_matrix(IMG_E0, K_L0, NK_L0, IMG_E1, K_L1, 0);
        finish(cst0, 0);

        init_acc(bias + 512);
        run_matrix(IMG_E1, K_L1, NK_L1,
                   (t + 1 < T_HIST) ? IMG_E0 : IMG_D0, K_L0, 1);
        finish(cst1, 144);
    }

    // zero the x/y slot so decoder starts from y0 = 0
    for (int i = tid; i < ROWS * 16; i += THREADS) {
        int r = i >> 4, c = i & 15;
        hcat[r * HS + 128 + c] = __float2half(0.0f);
    }
    __syncthreads();

    // ================= decoder =================
#pragma unroll 1
    for (int t = 0; t < T_FUT; ++t) {
        init_acc(bias + 1024);
        run_matrix(IMG_D0, K_L0, NK_L0, IMG_D1, K_L1, 0);
        finish(cst0, 0);

        init_acc(bias + 1536);
        run_matrix(IMG_D1, K_L1, NK_L1, IMG_D0, K_L0, 1);
        finish(cst1, 144);

        // head: dxy = h1 @ headW^T + headb ; write y back into hcat fp16
        if (tid < ROWS * 2) {
            int r = tid >> 1, d = tid & 1;
            float s = headbs[d];
            const __half* hr = hcat + r * HS + 144;
            const float*  hw = headWs + d * 128;
#pragma unroll 8
            for (int jj = 0; jj < HID; ++jj)
                s += __half2float(hr[jj]) * hw[jj];
            out[(size_t)(brow + r) * (T_FUT * 2) + t * 2 + d] = s;
            hcat[r * HS + 128 + d] = __float2half(s);
        }
        __syncthreads();   // y visible before next decL0 reads
    }

    cp_wait0();   // drain dangling prefetch before CTA exit
}

extern "C" void kernel_launch(void* const* d_in, const int* in_sizes, int n_in,
                              void* d_out, int out_size)
{
    const float* hist  = (const float*)d_in[0];
    const float* eWih0 = (const float*)d_in[1];
    const float* eWhh0 = (const float*)d_in[2];
    const float* ebih0 = (const float*)d_in[3];
    const float* ebhh0 = (const float*)d_in[4];
    const float* eWih1 = (const float*)d_in[5];
    const float* eWhh1 = (const float*)d_in[6];
    const float* ebih1 = (const float*)d_in[7];
    const float* ebhh1 = (const float*)d_in[8];
    const float* dWih0 = (const float*)d_in[9];
    const float* dWhh0 = (const float*)d_in[10];
    const float* dbih0 = (const float*)d_in[11];
    const float* dbhh0 = (const float*)d_in[12];
    const float* dWih1 = (const float*)d_in[13];
    const float* dWhh1 = (const float*)d_in[14];
    const float* dbih1 = (const float*)d_in[15];
    const float* dbhh1 = (const float*)d_in[16];
    const float* headW = (const float*)d_in[17];
    const float* headb = (const float*)d_in[18];

    int B = in_sizes[0] / (T_HIST * FIN);
    int grid = B / ROWS;

    prep_weights<<<(WIMG_TOTAL + 511) / 512, 512>>>(
        eWih0, eWhh0, eWih1, eWhh1, dWih0, dWhh0, dWih1, dWhh1);

    cudaFuncSetAttribute(lstm_mma_kernel,
                         cudaFuncAttributeMaxDynamicSharedMemorySize, SMEM_BYTES);

    lstm_mma_kernel<<<grid, THREADS, SMEM_BYTES>>>(
        hist, ebih0, ebhh0, ebih1, ebhh1, dbih0, dbhh0, dbih1, dbhh1,
        headW, headb, (float*)d_out);
}